// round 14
// baseline (speedup 1.0000x reference)
#include <cuda_runtime.h>
#include <math.h>

#define T_TOK 4096
#define H_DIM 1024
#define I_DIM 4096
#define E_NUM 8
#define TOTAL_SLOTS (2 * T_TOK)
#define SLOT_PAD (TOTAL_SLOTS + 128)

// -------- scratch (static __device__ arrays; no allocation) --------
__device__ float g_xhat[(size_t)T_TOK * H_DIM];
__device__ float g_y2[(size_t)TOTAL_SLOTS * H_DIM];
__device__ unsigned short g_a1h[(size_t)SLOT_PAD * H_DIM];       // fp16 A1
__device__ unsigned short g_hh[(size_t)SLOT_PAD * I_DIM];        // fp16 h
__device__ unsigned short g_w1f[(size_t)E_NUM * H_DIM * I_DIM];  // fp16 w1
__device__ unsigned short g_w2f[(size_t)E_NUM * I_DIM * H_DIM];  // fp16 w2
__device__ int   g_rows[TOTAL_SLOTS];
__device__ float g_slot_w[TOTAL_SLOTS];
__device__ int   g_slot_e[TOTAL_SLOTS];
__device__ int   g_tok_slot[T_TOK * 2];
__device__ int   g_sel[T_TOK * 2];
__device__ float g_selw[T_TOK * 2];
__device__ int   g_counts[E_NUM];
__device__ int   g_offsets[E_NUM];

// -------- helpers --------
__device__ __forceinline__ float warp_sum(float v) {
    #pragma unroll
    for (int o = 16; o > 0; o >>= 1) v += __shfl_down_sync(0xffffffffu, v, o);
    return v;
}

__device__ __forceinline__ unsigned short f16rn(float x) {
    unsigned short h;
    asm("cvt.rn.f16.f32 %0, %1;" : "=h"(h) : "f"(x));
    return h;
}

__device__ __forceinline__ unsigned smem_addr_u32(const void* p) {
    unsigned addr;
    asm("{ .reg .u64 tmp; cvta.to.shared.u64 tmp, %1; cvt.u32.u64 %0, tmp; }"
        : "=r"(addr) : "l"(p));
    return addr;
}

__device__ __forceinline__ void ldsm4(unsigned* r, unsigned a) {
    asm volatile("ldmatrix.sync.aligned.m8n8.x4.shared.b16 {%0,%1,%2,%3}, [%4];"
                 : "=r"(r[0]), "=r"(r[1]), "=r"(r[2]), "=r"(r[3]) : "r"(a));
}

__device__ __forceinline__ void ldsm4t(unsigned* r, unsigned a) {
    asm volatile("ldmatrix.sync.aligned.m8n8.x4.trans.shared.b16 {%0,%1,%2,%3}, [%4];"
                 : "=r"(r[0]), "=r"(r[1]), "=r"(r[2]), "=r"(r[3]) : "r"(a));
}

__device__ __forceinline__ void mma_f16(float* c, const unsigned* a, const unsigned* b) {
    asm volatile(
        "mma.sync.aligned.m16n8k16.row.col.f32.f16.f16.f32 "
        "{%0,%1,%2,%3}, {%4,%5,%6,%7}, {%8,%9}, {%0,%1,%2,%3};"
        : "+f"(c[0]), "+f"(c[1]), "+f"(c[2]), "+f"(c[3])
        : "r"(a[0]), "r"(a[1]), "r"(a[2]), "r"(a[3]), "r"(b[0]), "r"(b[1]));
}

__device__ __forceinline__ void cp16(unsigned dst, const void* src) {
    asm volatile("cp.async.cg.shared.global [%0], [%1], 16;" :: "r"(dst), "l"(src));
}

__global__ void init_kernel() {
    if (threadIdx.x < E_NUM) g_counts[threadIdx.x] = 0;
}

// -------- 1. router --------
__global__ void router_kernel(const float* __restrict__ x,
                              const float* __restrict__ rlnw,
                              const float* __restrict__ rlnb,
                              const float* __restrict__ rw,
                              const float* __restrict__ rb)
{
    const int t = blockIdx.x;
    const int tid = threadIdx.x;
    const float4 v = ((const float4*)(x + (size_t)t * H_DIM))[tid];

    float s  = v.x + v.y + v.z + v.w;
    float ss = v.x * v.x + v.y * v.y + v.z * v.z + v.w * v.w;

    __shared__ float s1[8];
    __shared__ float s2[8];
    float ws = warp_sum(s);
    float wss = warp_sum(ss);
    const int w = tid >> 5;
    const int l = tid & 31;
    if (l == 0) { s1[w] = ws; s2[w] = wss; }
    __syncthreads();
    if (w == 0) {
        float a = (l < 8) ? s1[l] : 0.0f;
        float b = (l < 8) ? s2[l] : 0.0f;
        a = warp_sum(a);
        b = warp_sum(b);
        if (l == 0) { s1[0] = a; s2[0] = b; }
    }
    __syncthreads();
    const float invH = 1.0f / (float)H_DIM;
    const float mu   = s1[0] * invH;
    const float var  = s2[0] * invH - mu * mu;
    const float rstd = rsqrtf(var + 1e-5f);

    float4 xh;
    xh.x = (v.x - mu) * rstd;
    xh.y = (v.y - mu) * rstd;
    xh.z = (v.z - mu) * rstd;
    xh.w = (v.w - mu) * rstd;
    ((float4*)(g_xhat + (size_t)t * H_DIM))[tid] = xh;

    const float4 lw = ((const float4*)rlnw)[tid];
    const float4 lb = ((const float4*)rlnb)[tid];
    float yv[4];
    yv[0] = xh.x * lw.x + lb.x;
    yv[1] = xh.y * lw.y + lb.y;
    yv[2] = xh.z * lw.z + lb.z;
    yv[3] = xh.w * lw.w + lb.w;

    float acc[E_NUM];
    #pragma unroll
    for (int e = 0; e < E_NUM; e++) acc[e] = 0.0f;
    const int h0 = tid * 4;
    #pragma unroll
    for (int j = 0; j < 4; j++) {
        const float4 r0 = *(const float4*)(rw + (size_t)(h0 + j) * E_NUM);
        const float4 r1 = *(const float4*)(rw + (size_t)(h0 + j) * E_NUM + 4);
        acc[0] += yv[j] * r0.x; acc[1] += yv[j] * r0.y;
        acc[2] += yv[j] * r0.z; acc[3] += yv[j] * r0.w;
        acc[4] += yv[j] * r1.x; acc[5] += yv[j] * r1.y;
        acc[6] += yv[j] * r1.z; acc[7] += yv[j] * r1.w;
    }

    __shared__ float racc[8][E_NUM];
    #pragma unroll
    for (int e = 0; e < E_NUM; e++) {
        float a = warp_sum(acc[e]);
        if (l == 0) racc[w][e] = a;
    }
    __syncthreads();

    __shared__ float slog[E_NUM];
    if (tid < E_NUM) {
        float lg = rb[tid];
        #pragma unroll
        for (int ww = 0; ww < 8; ww++) lg += racc[ww][tid];
        slog[tid] = lg;
    }
    __syncthreads();

    if (tid == 0) {
        float b0 = -1e30f; int i0 = 0;
        #pragma unroll
        for (int e = 0; e < E_NUM; e++) {
            if (slog[e] > b0) { b0 = slog[e]; i0 = e; }
        }
        float b1 = -1e30f; int i1 = 0;
        #pragma unroll
        for (int e = 0; e < E_NUM; e++) {
            if (e != i0 && slog[e] > b1) { b1 = slog[e]; i1 = e; }
        }
        const float e1 = expf(b1 - b0);
        const float inv = 1.0f / (1.0f + e1);
        g_sel[t * 2 + 0] = i0; g_selw[t * 2 + 0] = inv;
        g_sel[t * 2 + 1] = i1; g_selw[t * 2 + 1] = e1 * inv;
        atomicAdd(&g_counts[i0], 1);
        atomicAdd(&g_counts[i1], 1);
    }
}

// -------- 2. single-block: offsets + slot assignment --------
__global__ void assign_all_kernel() {
    __shared__ int scur[E_NUM];
    const int tid = threadIdx.x;   // 1024
    if (tid == 0) {
        int o = 0;
        for (int e = 0; e < E_NUM; e++) {
            scur[e] = o;
            g_offsets[e] = o;
            o += g_counts[e];
        }
    }
    __syncthreads();
    for (int t = tid; t < T_TOK; t += 1024) {
        #pragma unroll
        for (int k = 0; k < 2; k++) {
            const int e = g_sel[t * 2 + k];
            const int slot = atomicAdd(&scur[e], 1);
            g_rows[slot]   = t;
            g_slot_w[slot] = g_selw[t * 2 + k];
            g_slot_e[slot] = e;
            g_tok_slot[t * 2 + k] = slot;
        }
    }
}

// -------- 3. build A1: affine(gather(xhat)) -> fp16 --------
__global__ void build_a1_kernel(const float* __restrict__ elnw,
                                const float* __restrict__ elnb)
{
    const int slot = blockIdx.x;
    const int tid  = threadIdx.x;
    const int tok  = g_rows[slot];
    const int e    = g_slot_e[slot];
    const float4 xv = ((const float4*)(g_xhat + (size_t)tok * H_DIM))[tid];
    const float4 lw = ((const float4*)(elnw + (size_t)e * H_DIM))[tid];
    const float4 lb = ((const float4*)(elnb + (size_t)e * H_DIM))[tid];
    float v0 = xv.x * lw.x + lb.x;
    float v1 = xv.y * lw.y + lb.y;
    float v2 = xv.z * lw.z + lb.z;
    float v3 = xv.w * lw.w + lb.w;
    uint2 hp;
    hp.x = (unsigned)f16rn(v0) | ((unsigned)f16rn(v1) << 16);
    hp.y = (unsigned)f16rn(v2) | ((unsigned)f16rn(v3) << 16);
    ((uint2*)(g_a1h + (size_t)slot * H_DIM))[tid] = hp;
}

// -------- 4. element-wise weight convert fp32 -> fp16 --------
__global__ void split_w_kernel(const float* __restrict__ W,
                               unsigned short* __restrict__ of,
                               int total4)
{
    const int idx = blockIdx.x * blockDim.x + threadIdx.x;
    if (idx < total4) {
        const float4 v = ((const float4*)W)[idx];
        uint2 p;
        p.x = (unsigned)f16rn(v.x) | ((unsigned)f16rn(v.y) << 16);
        p.y = (unsigned)f16rn(v.z) | ((unsigned)f16rn(v.w) << 16);
        ((uint2*)of)[idx] = p;
    }
}

// ================= 3-stage cp.async pipelined fp16 GEMM ==================
#define GBK 64
#define NSTAGE 3
#define A_PITCH 144
#define B_PITCH 272
#define O_A 0
#define O_B 18432
#define BUF_STRIDE 35840
#define SMEM_DYN (NSTAGE * BUF_STRIDE)

__device__ __forceinline__ void load_tiles(
    unsigned smu, int stage,
    const unsigned short* Af, int arow0, int astride,
    const unsigned short* Bf, int n0, int bstride,
    int k0, int tid)
{
    const unsigned su = smu + stage * BUF_STRIDE;
    #pragma unroll
    for (int i = 0; i < 4; i++) {
        const int idx = tid + i * 256;
        const int row = idx >> 3;
        const int u   = idx & 7;
        const size_t src = (size_t)(arow0 + row) * astride + k0 + u * 8;
        cp16(su + O_A + row * A_PITCH + u * 16, Af + src);
    }
    #pragma unroll
    for (int i = 0; i < 4; i++) {
        const int idx = tid + i * 256;
        const int row = idx >> 4;
        const int u   = idx & 15;
        const size_t src = (size_t)(k0 + row) * bstride + n0 + u * 8;
        cp16(su + O_B + row * B_PITCH + u * 16, Bf + src);
    }
    asm volatile("cp.async.commit_group;" ::: "memory");
}

__device__ __forceinline__ void compute_chunk(
    unsigned smu, int stage, float c[4][4][4],
    int wm, int wn, int frow, int fcol)
{
    const unsigned su = smu + stage * BUF_STRIDE;
    #pragma unroll
    for (int kk = 0; kk < GBK; kk += 16) {
        unsigned bb[4][2];
        #pragma unroll
        for (int np = 0; np < 2; np++) {
            unsigned tmp[4];
            unsigned ad = su + O_B + (kk + frow) * B_PITCH + (wn * 32 + np * 16 + fcol) * 2;
            ldsm4t(tmp, ad);
            bb[np * 2 + 0][0] = tmp[0]; bb[np * 2 + 0][1] = tmp[1];
            bb[np * 2 + 1][0] = tmp[2]; bb[np * 2 + 1][1] = tmp[3];
        }
        #pragma unroll
        for (int ms = 0; ms < 4; ms++) {
            unsigned ah[4];
            unsigned ad = su + O_A + (wm * 64 + ms * 16 + frow) * A_PITCH + (kk + fcol) * 2;
            ldsm4(ah, ad);
            #pragma unroll
            for (int ns = 0; ns < 4; ns++) {
                mma_f16(c[ms][ns], ah, bb[ns]);
            }
        }
    }
}

// -------- GEMM1: h = gelu(A1 @ w1 + b1) -> g_hh (fp16) --------
__global__ void __launch_bounds__(256, 2)
gemm1_cp_kernel(const float* __restrict__ b1)
{
    extern __shared__ char smem[];
    const int e   = blockIdx.z;
    const int beg = g_offsets[e];
    const int cnt = g_counts[e];
    if ((int)blockIdx.y * 128 >= cnt) return;
    const int row0 = beg + blockIdx.y * 128;
    const int end  = beg + cnt;
    const int n0   = blockIdx.x * 128;

    const unsigned short* Bf = g_w1f + (size_t)e * H_DIM * I_DIM;

    const unsigned smu = smem_addr_u32(smem);
    const int tid = threadIdx.x;
    const int lane = tid & 31;
    const int warp = tid >> 5;
    const int wm = warp >> 2;
    const int wn = warp & 3;
    const int frow = lane & 15;
    const int fcol = (lane >> 4) * 8;

    float c[4][4][4];
    #pragma unroll
    for (int i = 0; i < 4; i++)
        #pragma unroll
        for (int j = 0; j < 4; j++)
            #pragma unroll
            for (int q = 0; q < 4; q++) c[i][j][q] = 0.0f;

    const int NK = H_DIM / GBK;   // 16
    load_tiles(smu, 0, g_a1h, row0, H_DIM, Bf, n0, I_DIM, 0, tid);
    load_tiles(smu, 1, g_a1h, row0, H_DIM, Bf, n0, I_DIM, GBK, tid);
    int stage_c = 0;
    int stage_p = 2;
    #pragma unroll 1
    for (int kt = 0; kt < NK; kt++) {
        if (kt + 1 < NK) {
            asm volatile("cp.async.wait_group 1;" ::: "memory");
        } else {
            asm volatile("cp.async.wait_group 0;" ::: "memory");
        }
        __syncthreads();
        if (kt + 2 < NK) {
            load_tiles(smu, stage_p, g_a1h, row0, H_DIM, Bf, n0, I_DIM,
                       (kt + 2) * GBK, tid);
        }
        compute_chunk(smu, stage_c, c, wm, wn, frow, fcol);
        stage_c = (stage_c == NSTAGE - 1) ? 0 : stage_c + 1;
        stage_p = (stage_p == NSTAGE - 1) ? 0 : stage_p + 1;
    }

    const float* bp = b1 + (size_t)e * I_DIM;
    const int r  = lane >> 2;
    const int cq = (lane & 3) * 2;
    #pragma unroll
    for (int ms = 0; ms < 4; ms++) {
        #pragma unroll
        for (int half = 0; half < 2; half++) {
            const int slot = row0 + wm * 64 + ms * 16 + r + half * 8;
            if (slot < end) {
                unsigned short* oh = g_hh + (size_t)slot * I_DIM;
                #pragma unroll
                for (int ns = 0; ns < 4; ns++) {
                    const int col = n0 + wn * 32 + ns * 8 + cq;
                    float v0 = c[ms][ns][half * 2 + 0] + bp[col];
                    float v1 = c[ms][ns][half * 2 + 1] + bp[col + 1];
                    v0 = 0.5f * v0 * (1.0f + erff(v0 * 0.70710678118654752f));
                    v1 = 0.5f * v1 * (1.0f + erff(v1 * 0.70710678118654752f));
                    *(unsigned*)(oh + col) =
                        (unsigned)f16rn(v0) | ((unsigned)f16rn(v1) << 16);
                }
            }
        }
    }
}

// -------- GEMM2: y2 = (h @ w2 + b2) * slot_w -> g_y2 (fp32) --------
__global__ void __launch_bounds__(256, 2)
gemm2_cp_kernel(const float* __restrict__ b2)
{
    extern __shared__ char smem[];
    const int e   = blockIdx.z;
    const int beg = g_offsets[e];
    const int cnt = g_counts[e];
    if ((int)blockIdx.y * 128 >= cnt) return;
    const int row0 = beg + blockIdx.y * 128;
    const int end  = beg + cnt;
    const int n0   = blockIdx.x * 128;

    const unsigned short* Bf = g_w2f + (size_t)e * I_DIM * H_DIM;

    const unsigned smu = smem_addr_u32(smem);
    const int tid = threadIdx.x;
    const int lane = tid & 31;
    const int warp = tid >> 5;
    const int wm = warp >> 2;
    const int wn = warp & 3;
    const int frow = lane & 15;
    const int fcol = (lane >> 4) * 8;

    float c[4][4][4];
    #pragma unroll
    for (int i = 0; i < 4; i++)
        #pragma unroll
        for (int j = 0; j < 4; j++)
            #pragma unroll
            for (int q = 0; q < 4; q++) c[i][j][q] = 0.0f;

    const int NK = I_DIM / GBK;   // 64
    load_tiles(smu, 0, g_hh, row0, I_DIM, Bf, n0, H_DIM, 0, tid);
    load_tiles(smu, 1, g_hh, row0, I_DIM, Bf, n0, H_DIM, GBK, tid);
    int stage_c = 0;
    int stage_p = 2;
    #pragma unroll 1
    for (int kt = 0; kt < NK; kt++) {
        if (kt + 1 < NK) {
            asm volatile("cp.async.wait_group 1;" ::: "memory");
        } else {
            asm volatile("cp.async.wait_group 0;" ::: "memory");
        }
        __syncthreads();
        if (kt + 2 < NK) {
            load_tiles(smu, stage_p, g_hh, row0, I_DIM, Bf, n0, H_DIM,
                       (kt + 2) * GBK, tid);
        }
        compute_chunk(smu, stage_c, c, wm, wn, frow, fcol);
        stage_c = (stage_c == NSTAGE - 1) ? 0 : stage_c + 1;
        stage_p = (stage_p == NSTAGE - 1) ? 0 : stage_p + 1;
    }

    const float* bp = b2 + (size_t)e * H_DIM;
    const int r  = lane >> 2;
    const int cq = (lane & 3) * 2;
    #pragma unroll
    for (int ms = 0; ms < 4; ms++) {
        #pragma unroll
        for (int half = 0; half < 2; half++) {
            const int slot = row0 + wm * 64 + ms * 16 + r + half * 8;
            if (slot < end) {
                const float wgt = g_slot_w[slot];
                float* orow = g_y2 + (size_t)slot * H_DIM;
                #pragma unroll
                for (int ns = 0; ns < 4; ns++) {
                    const int col = n0 + wn * 32 + ns * 8 + cq;
                    float v0 = (c[ms][ns][half * 2 + 0] + bp[col]) * wgt;
                    float v1 = (c[ms][ns][half * 2 + 1] + bp[col + 1]) * wgt;
                    *(float2*)(orow + col) = make_float2(v0, v1);
                }
            }
        }
    }
}

// -------- combine two experts + final LayerNorm --------
__global__ void combine_ln_kernel(const float* __restrict__ olnw,
                                  const float* __restrict__ olnb,
                                  float* __restrict__ out)
{
    const int t = blockIdx.x;
    const int tid = threadIdx.x;
    const int sA = g_tok_slot[t * 2 + 0];
    const int sB = g_tok_slot[t * 2 + 1];
    const float4 a = ((const float4*)(g_y2 + (size_t)sA * H_DIM))[tid];
    const float4 b = ((const float4*)(g_y2 + (size_t)sB * H_DIM))[tid];
    float4 cc;
    cc.x = a.x + b.x; cc.y = a.y + b.y; cc.z = a.z + b.z; cc.w = a.w + b.w;

    float s  = cc.x + cc.y + cc.z + cc.w;
    float ss = cc.x * cc.x + cc.y * cc.y + cc.z * cc.z + cc.w * cc.w;

    __shared__ float s1m[8];
    __shared__ float s2m[8];
    float wsv = warp_sum(s);
    float wss = warp_sum(ss);
    const int w = tid >> 5;
    const int l = tid & 31;
    if (l == 0) { s1m[w] = wsv; s2m[w] = wss; }
    __syncthreads();
    if (w == 0) {
        float x1 = (l < 8) ? s1m[l] : 0.0f;
        float x2 = (l < 8) ? s2m[l] : 0.0f;
        x1 = warp_sum(x1);
        x2 = warp_sum(x2);
        if (l == 0) { s1m[0] = x1; s2m[0] = x2; }
    }
    __syncthreads();
    const float invH = 1.0f / (float)H_DIM;
    const float mu   = s1m[0] * invH;
    const float var  = s2m[0] * invH - mu * mu;
    const float rstd = rsqrtf(var + 1e-5f);

    const float4 lw = ((const float4*)olnw)[tid];
    const float4 lb = ((const float4*)olnb)[tid];
    float4 o;
    o.x = (cc.x - mu) * rstd * lw.x + lb.x;
    o.y = (cc.y - mu) * rstd * lw.y + lb.y;
    o.z = (cc.z - mu) * rstd * lw.z + lb.z;
    o.w = (cc.w - mu) * rstd * lw.w + lb.w;
    ((float4*)(out + (size_t)t * H_DIM))[tid] = o;
}

// -------- launch --------
extern "C" void kernel_launch(void* const* d_in, const int* in_sizes, int n_in,
                              void* d_out, int out_size)
{
    const float* x    = (const float*)d_in[0];
    const float* rlnw = (const float*)d_in[1];
    const float* rlnb = (const float*)d_in[2];
    const float* rw   = (const float*)d_in[3];
    const float* rb   = (const float*)d_in[4];
    const float* elnw = (const float*)d_in[5];
    const float* elnb = (const float*)d_in[6];
    const float* w1   = (const float*)d_in[7];
    const float* b1   = (const float*)d_in[8];
    const float* w2   = (const float*)d_in[9];
    const float* b2   = (const float*)d_in[10];
    const float* olnw = (const float*)d_in[11];
    const float* olnb = (const float*)d_in[12];
    float* out = (float*)d_out;

    cudaFuncSetAttribute(gemm1_cp_kernel, cudaFuncAttributeMaxDynamicSharedMemorySize, SMEM_DYN);
    cudaFuncSetAttribute(gemm2_cp_kernel, cudaFuncAttributeMaxDynamicSharedMemorySize, SMEM_DYN);

    unsigned short* w1f = 0; cudaGetSymbolAddress((void**)&w1f, g_w1f);
    unsigned short* w2f = 0; cudaGetSymbolAddress((void**)&w2f, g_w2f);

    const int wtotal4 = E_NUM * H_DIM * I_DIM / 4;

    init_kernel<<<1, 32>>>();
    router_kernel<<<T_TOK, 256>>>(x, rlnw, rlnb, rw, rb);
    assign_all_kernel<<<1, 1024>>>();
    build_a1_kernel<<<TOTAL_SLOTS, 256>>>(elnw, elnb);
    split_w_kernel<<<wtotal4 / 256, 256>>>(w1, w1f, wtotal4);
    gemm1_cp_kernel<<<dim3(I_DIM / 128, 32, E_NUM), 256, SMEM_DYN>>>(b1);
    split_w_kernel<<<wtotal4 / 256, 256>>>(w2, w2f, wtotal4);
    gemm2_cp_kernel<<<dim3(H_DIM / 128, 32, E_NUM), 256, SMEM_DYN>>>(b2);
    combine_ln_kernel<<<T_TOK, 256>>>(olnw, olnb, out);
}

// round 16
// speedup vs baseline: 1.0078x; 1.0078x over previous
#include <cuda_runtime.h>
#include <math.h>

#define T_TOK 4096
#define H_DIM 1024
#define I_DIM 4096
#define E_NUM 8
#define TOTAL_SLOTS (2 * T_TOK)
#define SLOT_PAD (TOTAL_SLOTS + 128)

// -------- scratch (static __device__ arrays; no allocation) --------
__device__ float g_xhat[(size_t)T_TOK * H_DIM];
__device__ float g_y2[(size_t)TOTAL_SLOTS * H_DIM];
__device__ unsigned short g_a1h[(size_t)SLOT_PAD * H_DIM];       // fp16 A1
__device__ unsigned short g_hh[(size_t)SLOT_PAD * I_DIM];        // fp16 h
__device__ unsigned short g_w1f[(size_t)E_NUM * H_DIM * I_DIM];  // fp16 w1
__device__ unsigned short g_w2f[(size_t)E_NUM * I_DIM * H_DIM];  // fp16 w2
__device__ int   g_rows[TOTAL_SLOTS];
__device__ float g_slot_w[TOTAL_SLOTS];
__device__ int   g_slot_e[TOTAL_SLOTS];
__device__ int   g_tok_slot[T_TOK * 2];
__device__ int   g_sel[T_TOK * 2];
__device__ float g_selw[T_TOK * 2];
__device__ int   g_counts[E_NUM];
__device__ int   g_offsets[E_NUM];

// -------- helpers --------
__device__ __forceinline__ float warp_sum(float v) {
    #pragma unroll
    for (int o = 16; o > 0; o >>= 1) v += __shfl_down_sync(0xffffffffu, v, o);
    return v;
}

__device__ __forceinline__ unsigned short f16rn(float x) {
    unsigned short h;
    asm("cvt.rn.f16.f32 %0, %1;" : "=h"(h) : "f"(x));
    return h;
}

__device__ __forceinline__ unsigned smem_addr_u32(const void* p) {
    unsigned addr;
    asm("{ .reg .u64 tmp; cvta.to.shared.u64 tmp, %1; cvt.u32.u64 %0, tmp; }"
        : "=r"(addr) : "l"(p));
    return addr;
}

__device__ __forceinline__ void ldsm4(unsigned* r, unsigned a) {
    asm volatile("ldmatrix.sync.aligned.m8n8.x4.shared.b16 {%0,%1,%2,%3}, [%4];"
                 : "=r"(r[0]), "=r"(r[1]), "=r"(r[2]), "=r"(r[3]) : "r"(a));
}

__device__ __forceinline__ void ldsm4t(unsigned* r, unsigned a) {
    asm volatile("ldmatrix.sync.aligned.m8n8.x4.trans.shared.b16 {%0,%1,%2,%3}, [%4];"
                 : "=r"(r[0]), "=r"(r[1]), "=r"(r[2]), "=r"(r[3]) : "r"(a));
}

__device__ __forceinline__ void mma_f16(float* c, const unsigned* a, const unsigned* b) {
    asm volatile(
        "mma.sync.aligned.m16n8k16.row.col.f32.f16.f16.f32 "
        "{%0,%1,%2,%3}, {%4,%5,%6,%7}, {%8,%9}, {%0,%1,%2,%3};"
        : "+f"(c[0]), "+f"(c[1]), "+f"(c[2]), "+f"(c[3])
        : "r"(a[0]), "r"(a[1]), "r"(a[2]), "r"(a[3]), "r"(b[0]), "r"(b[1]));
}

__device__ __forceinline__ void cp16(unsigned dst, const void* src) {
    asm volatile("cp.async.cg.shared.global [%0], [%1], 16;" :: "r"(dst), "l"(src));
}

__global__ void init_kernel() {
    if (threadIdx.x < E_NUM) g_counts[threadIdx.x] = 0;
}

// -------- 1. router --------
__global__ void router_kernel(const float* __restrict__ x,
                              const float* __restrict__ rlnw,
                              const float* __restrict__ rlnb,
                              const float* __restrict__ rw,
                              const float* __restrict__ rb)
{
    const int t = blockIdx.x;
    const int tid = threadIdx.x;
    const float4 v = ((const float4*)(x + (size_t)t * H_DIM))[tid];

    float s  = v.x + v.y + v.z + v.w;
    float ss = v.x * v.x + v.y * v.y + v.z * v.z + v.w * v.w;

    __shared__ float s1[8];
    __shared__ float s2[8];
    float ws = warp_sum(s);
    float wss = warp_sum(ss);
    const int w = tid >> 5;
    const int l = tid & 31;
    if (l == 0) { s1[w] = ws; s2[w] = wss; }
    __syncthreads();
    if (w == 0) {
        float a = (l < 8) ? s1[l] : 0.0f;
        float b = (l < 8) ? s2[l] : 0.0f;
        a = warp_sum(a);
        b = warp_sum(b);
        if (l == 0) { s1[0] = a; s2[0] = b; }
    }
    __syncthreads();
    const float invH = 1.0f / (float)H_DIM;
    const float mu   = s1[0] * invH;
    const float var  = s2[0] * invH - mu * mu;
    const float rstd = rsqrtf(var + 1e-5f);

    float4 xh;
    xh.x = (v.x - mu) * rstd;
    xh.y = (v.y - mu) * rstd;
    xh.z = (v.z - mu) * rstd;
    xh.w = (v.w - mu) * rstd;
    ((float4*)(g_xhat + (size_t)t * H_DIM))[tid] = xh;

    const float4 lw = ((const float4*)rlnw)[tid];
    const float4 lb = ((const float4*)rlnb)[tid];
    float yv[4];
    yv[0] = xh.x * lw.x + lb.x;
    yv[1] = xh.y * lw.y + lb.y;
    yv[2] = xh.z * lw.z + lb.z;
    yv[3] = xh.w * lw.w + lb.w;

    float acc[E_NUM];
    #pragma unroll
    for (int e = 0; e < E_NUM; e++) acc[e] = 0.0f;
    const int h0 = tid * 4;
    #pragma unroll
    for (int j = 0; j < 4; j++) {
        const float4 r0 = *(const float4*)(rw + (size_t)(h0 + j) * E_NUM);
        const float4 r1 = *(const float4*)(rw + (size_t)(h0 + j) * E_NUM + 4);
        acc[0] += yv[j] * r0.x; acc[1] += yv[j] * r0.y;
        acc[2] += yv[j] * r0.z; acc[3] += yv[j] * r0.w;
        acc[4] += yv[j] * r1.x; acc[5] += yv[j] * r1.y;
        acc[6] += yv[j] * r1.z; acc[7] += yv[j] * r1.w;
    }

    __shared__ float racc[8][E_NUM];
    #pragma unroll
    for (int e = 0; e < E_NUM; e++) {
        float a = warp_sum(acc[e]);
        if (l == 0) racc[w][e] = a;
    }
    __syncthreads();

    __shared__ float slog[E_NUM];
    if (tid < E_NUM) {
        float lg = rb[tid];
        #pragma unroll
        for (int ww = 0; ww < 8; ww++) lg += racc[ww][tid];
        slog[tid] = lg;
    }
    __syncthreads();

    if (tid == 0) {
        float b0 = -1e30f; int i0 = 0;
        #pragma unroll
        for (int e = 0; e < E_NUM; e++) {
            if (slog[e] > b0) { b0 = slog[e]; i0 = e; }
        }
        float b1 = -1e30f; int i1 = 0;
        #pragma unroll
        for (int e = 0; e < E_NUM; e++) {
            if (e != i0 && slog[e] > b1) { b1 = slog[e]; i1 = e; }
        }
        const float e1 = expf(b1 - b0);
        const float inv = 1.0f / (1.0f + e1);
        g_sel[t * 2 + 0] = i0; g_selw[t * 2 + 0] = inv;
        g_sel[t * 2 + 1] = i1; g_selw[t * 2 + 1] = e1 * inv;
        atomicAdd(&g_counts[i0], 1);
        atomicAdd(&g_counts[i1], 1);
    }
}

// -------- 2. single-block: offsets + slot assignment --------
__global__ void assign_all_kernel() {
    __shared__ int scur[E_NUM];
    const int tid = threadIdx.x;   // 1024
    if (tid == 0) {
        int o = 0;
        for (int e = 0; e < E_NUM; e++) {
            scur[e] = o;
            g_offsets[e] = o;
            o += g_counts[e];
        }
    }
    __syncthreads();
    for (int t = tid; t < T_TOK; t += 1024) {
        #pragma unroll
        for (int k = 0; k < 2; k++) {
            const int e = g_sel[t * 2 + k];
            const int slot = atomicAdd(&scur[e], 1);
            g_rows[slot]   = t;
            g_slot_w[slot] = g_selw[t * 2 + k];
            g_slot_e[slot] = e;
            g_tok_slot[t * 2 + k] = slot;
        }
    }
}

// -------- 3. build A1: affine(gather(xhat)) -> fp16 --------
__global__ void build_a1_kernel(const float* __restrict__ elnw,
                                const float* __restrict__ elnb)
{
    const int slot = blockIdx.x;
    const int tid  = threadIdx.x;
    const int tok  = g_rows[slot];
    const int e    = g_slot_e[slot];
    const float4 xv = ((const float4*)(g_xhat + (size_t)tok * H_DIM))[tid];
    const float4 lw = ((const float4*)(elnw + (size_t)e * H_DIM))[tid];
    const float4 lb = ((const float4*)(elnb + (size_t)e * H_DIM))[tid];
    float v0 = xv.x * lw.x + lb.x;
    float v1 = xv.y * lw.y + lb.y;
    float v2 = xv.z * lw.z + lb.z;
    float v3 = xv.w * lw.w + lb.w;
    uint2 hp;
    hp.x = (unsigned)f16rn(v0) | ((unsigned)f16rn(v1) << 16);
    hp.y = (unsigned)f16rn(v2) | ((unsigned)f16rn(v3) << 16);
    ((uint2*)(g_a1h + (size_t)slot * H_DIM))[tid] = hp;
}

// -------- 4. element-wise weight convert fp32 -> fp16 --------
__global__ void split_w_kernel(const float* __restrict__ W,
                               unsigned short* __restrict__ of,
                               int total4)
{
    const int idx = blockIdx.x * blockDim.x + threadIdx.x;
    if (idx < total4) {
        const float4 v = ((const float4*)W)[idx];
        uint2 p;
        p.x = (unsigned)f16rn(v.x) | ((unsigned)f16rn(v.y) << 16);
        p.y = (unsigned)f16rn(v.z) | ((unsigned)f16rn(v.w) << 16);
        ((uint2*)of)[idx] = p;
    }
}

// ================= 3-stage cp.async pipelined fp16 GEMM ==================
#define GBK 64
#define NSTAGE 3
#define A_PITCH 144
#define B_PITCH 272
#define O_A 0
#define O_B 18432
#define BUF_STRIDE 35840
#define SMEM_DYN (NSTAGE * BUF_STRIDE)

__device__ __forceinline__ void load_tiles(
    unsigned smu, int stage,
    const unsigned short* Af, int arow0, int astride,
    const unsigned short* Bf, int n0, int bstride,
    int k0, int tid)
{
    const unsigned su = smu + stage * BUF_STRIDE;
    #pragma unroll
    for (int i = 0; i < 4; i++) {
        const int idx = tid + i * 256;
        const int row = idx >> 3;
        const int u   = idx & 7;
        const size_t src = (size_t)(arow0 + row) * astride + k0 + u * 8;
        cp16(su + O_A + row * A_PITCH + u * 16, Af + src);
    }
    #pragma unroll
    for (int i = 0; i < 4; i++) {
        const int idx = tid + i * 256;
        const int row = idx >> 4;
        const int u   = idx & 15;
        const size_t src = (size_t)(k0 + row) * bstride + n0 + u * 8;
        cp16(su + O_B + row * B_PITCH + u * 16, Bf + src);
    }
    asm volatile("cp.async.commit_group;" ::: "memory");
}

__device__ __forceinline__ void compute_chunk(
    unsigned smu, int stage, float c[4][4][4],
    int wm, int wn, int frow, int fcol)
{
    const unsigned su = smu + stage * BUF_STRIDE;
    #pragma unroll
    for (int kk = 0; kk < GBK; kk += 16) {
        unsigned bb[4][2];
        #pragma unroll
        for (int np = 0; np < 2; np++) {
            unsigned tmp[4];
            unsigned ad = su + O_B + (kk + frow) * B_PITCH + (wn * 32 + np * 16 + fcol) * 2;
            ldsm4t(tmp, ad);
            bb[np * 2 + 0][0] = tmp[0]; bb[np * 2 + 0][1] = tmp[1];
            bb[np * 2 + 1][0] = tmp[2]; bb[np * 2 + 1][1] = tmp[3];
        }
        #pragma unroll
        for (int ms = 0; ms < 4; ms++) {
            unsigned ah[4];
            unsigned ad = su + O_A + (wm * 64 + ms * 16 + frow) * A_PITCH + (kk + fcol) * 2;
            ldsm4(ah, ad);
            #pragma unroll
            for (int ns = 0; ns < 4; ns++) {
                mma_f16(c[ms][ns], ah, bb[ns]);
            }
        }
    }
}

// -------- GEMM1: h = gelu(A1 @ w1 + b1) -> g_hh (fp16) --------
__global__ void __launch_bounds__(256, 2)
gemm1_cp_kernel(const float* __restrict__ b1)
{
    extern __shared__ char smem[];
    const int e   = blockIdx.z;
    const int beg = g_offsets[e];
    const int cnt = g_counts[e];
    if ((int)blockIdx.y * 128 >= cnt) return;
    const int row0 = beg + blockIdx.y * 128;
    const int end  = beg + cnt;
    const int n0   = blockIdx.x * 128;

    const unsigned short* Bf = g_w1f + (size_t)e * H_DIM * I_DIM;

    const unsigned smu = smem_addr_u32(smem);
    const int tid = threadIdx.x;
    const int lane = tid & 31;
    const int warp = tid >> 5;
    const int wm = warp >> 2;
    const int wn = warp & 3;
    const int frow = lane & 15;
    const int fcol = (lane >> 4) * 8;

    float c[4][4][4];
    #pragma unroll
    for (int i = 0; i < 4; i++)
        #pragma unroll
        for (int j = 0; j < 4; j++)
            #pragma unroll
            for (int q = 0; q < 4; q++) c[i][j][q] = 0.0f;

    const int NK = H_DIM / GBK;   // 16
    load_tiles(smu, 0, g_a1h, row0, H_DIM, Bf, n0, I_DIM, 0, tid);
    load_tiles(smu, 1, g_a1h, row0, H_DIM, Bf, n0, I_DIM, GBK, tid);
    int stage_c = 0;
    int stage_p = 2;
    #pragma unroll 1
    for (int kt = 0; kt < NK; kt++) {
        if (kt + 1 < NK) {
            asm volatile("cp.async.wait_group 1;" ::: "memory");
        } else {
            asm volatile("cp.async.wait_group 0;" ::: "memory");
        }
        __syncthreads();
        if (kt + 2 < NK) {
            load_tiles(smu, stage_p, g_a1h, row0, H_DIM, Bf, n0, I_DIM,
                       (kt + 2) * GBK, tid);
        }
        compute_chunk(smu, stage_c, c, wm, wn, frow, fcol);
        stage_c = (stage_c == NSTAGE - 1) ? 0 : stage_c + 1;
        stage_p = (stage_p == NSTAGE - 1) ? 0 : stage_p + 1;
    }

    const float* bp = b1 + (size_t)e * I_DIM;
    const int r  = lane >> 2;
    const int cq = (lane & 3) * 2;
    #pragma unroll
    for (int ms = 0; ms < 4; ms++) {
        #pragma unroll
        for (int half = 0; half < 2; half++) {
            const int slot = row0 + wm * 64 + ms * 16 + r + half * 8;
            if (slot < end) {
                unsigned short* oh = g_hh + (size_t)slot * I_DIM;
                #pragma unroll
                for (int ns = 0; ns < 4; ns++) {
                    const int col = n0 + wn * 32 + ns * 8 + cq;
                    float v0 = c[ms][ns][half * 2 + 0] + bp[col];
                    float v1 = c[ms][ns][half * 2 + 1] + bp[col + 1];
                    v0 = 0.5f * v0 * (1.0f + erff(v0 * 0.70710678118654752f));
                    v1 = 0.5f * v1 * (1.0f + erff(v1 * 0.70710678118654752f));
                    *(unsigned*)(oh + col) =
                        (unsigned)f16rn(v0) | ((unsigned)f16rn(v1) << 16);
                }
            }
        }
    }
}

// -------- GEMM2: y2 = (h @ w2 + b2) * slot_w -> g_y2 (fp32) --------
__global__ void __launch_bounds__(256, 2)
gemm2_cp_kernel(const float* __restrict__ b2)
{
    extern __shared__ char smem[];
    const int e   = blockIdx.z;
    const int beg = g_offsets[e];
    const int cnt = g_counts[e];
    if ((int)blockIdx.y * 128 >= cnt) return;
    const int row0 = beg + blockIdx.y * 128;
    const int end  = beg + cnt;
    const int n0   = blockIdx.x * 128;

    const unsigned short* Bf = g_w2f + (size_t)e * I_DIM * H_DIM;

    const unsigned smu = smem_addr_u32(smem);
    const int tid = threadIdx.x;
    const int lane = tid & 31;
    const int warp = tid >> 5;
    const int wm = warp >> 2;
    const int wn = warp & 3;
    const int frow = lane & 15;
    const int fcol = (lane >> 4) * 8;

    float c[4][4][4];
    #pragma unroll
    for (int i = 0; i < 4; i++)
        #pragma unroll
        for (int j = 0; j < 4; j++)
            #pragma unroll
            for (int q = 0; q < 4; q++) c[i][j][q] = 0.0f;

    const int NK = I_DIM / GBK;   // 64
    load_tiles(smu, 0, g_hh, row0, I_DIM, Bf, n0, H_DIM, 0, tid);
    load_tiles(smu, 1, g_hh, row0, I_DIM, Bf, n0, H_DIM, GBK, tid);
    int stage_c = 0;
    int stage_p = 2;
    #pragma unroll 1
    for (int kt = 0; kt < NK; kt++) {
        if (kt + 1 < NK) {
            asm volatile("cp.async.wait_group 1;" ::: "memory");
        } else {
            asm volatile("cp.async.wait_group 0;" ::: "memory");
        }
        __syncthreads();
        if (kt + 2 < NK) {
            load_tiles(smu, stage_p, g_hh, row0, I_DIM, Bf, n0, H_DIM,
                       (kt + 2) * GBK, tid);
        }
        compute_chunk(smu, stage_c, c, wm, wn, frow, fcol);
        stage_c = (stage_c == NSTAGE - 1) ? 0 : stage_c + 1;
        stage_p = (stage_p == NSTAGE - 1) ? 0 : stage_p + 1;
    }

    const float* bp = b2 + (size_t)e * H_DIM;
    const int r  = lane >> 2;
    const int cq = (lane & 3) * 2;
    #pragma unroll
    for (int ms = 0; ms < 4; ms++) {
        #pragma unroll
        for (int half = 0; half < 2; half++) {
            const int slot = row0 + wm * 64 + ms * 16 + r + half * 8;
            if (slot < end) {
                const float wgt = g_slot_w[slot];
                float* orow = g_y2 + (size_t)slot * H_DIM;
                #pragma unroll
                for (int ns = 0; ns < 4; ns++) {
                    const int col = n0 + wn * 32 + ns * 8 + cq;
                    float v0 = (c[ms][ns][half * 2 + 0] + bp[col]) * wgt;
                    float v1 = (c[ms][ns][half * 2 + 1] + bp[col + 1]) * wgt;
                    *(float2*)(orow + col) = make_float2(v0, v1);
                }
            }
        }
    }
}

// -------- combine two experts + final LayerNorm --------
__global__ void combine_ln_kernel(const float* __restrict__ olnw,
                                  const float* __restrict__ olnb,
                                  float* __restrict__ out)
{
    const int t = blockIdx.x;
    const int tid = threadIdx.x;
    const int sA = g_tok_slot[t * 2 + 0];
    const int sB = g_tok_slot[t * 2 + 1];
    const float4 a = ((const float4*)(g_y2 + (size_t)sA * H_DIM))[tid];
    const float4 b = ((const float4*)(g_y2 + (size_t)sB * H_DIM))[tid];
    float4 cc;
    cc.x = a.x + b.x; cc.y = a.y + b.y; cc.z = a.z + b.z; cc.w = a.w + b.w;

    float s  = cc.x + cc.y + cc.z + cc.w;
    float ss = cc.x * cc.x + cc.y * cc.y + cc.z * cc.z + cc.w * cc.w;

    __shared__ float s1m[8];
    __shared__ float s2m[8];
    float wsv = warp_sum(s);
    float wss = warp_sum(ss);
    const int w = tid >> 5;
    const int l = tid & 31;
    if (l == 0) { s1m[w] = wsv; s2m[w] = wss; }
    __syncthreads();
    if (w == 0) {
        float x1 = (l < 8) ? s1m[l] : 0.0f;
        float x2 = (l < 8) ? s2m[l] : 0.0f;
        x1 = warp_sum(x1);
        x2 = warp_sum(x2);
        if (l == 0) { s1m[0] = x1; s2m[0] = x2; }
    }
    __syncthreads();
    const float invH = 1.0f / (float)H_DIM;
    const float mu   = s1m[0] * invH;
    const float var  = s2m[0] * invH - mu * mu;
    const float rstd = rsqrtf(var + 1e-5f);

    const float4 lw = ((const float4*)olnw)[tid];
    const float4 lb = ((const float4*)olnb)[tid];
    float4 o;
    o.x = (cc.x - mu) * rstd * lw.x + lb.x;
    o.y = (cc.y - mu) * rstd * lw.y + lb.y;
    o.z = (cc.z - mu) * rstd * lw.z + lb.z;
    o.w = (cc.w - mu) * rstd * lw.w + lb.w;
    ((float4*)(out + (size_t)t * H_DIM))[tid] = o;
}

// -------- launch --------
extern "C" void kernel_launch(void* const* d_in, const int* in_sizes, int n_in,
                              void* d_out, int out_size)
{
    const float* x    = (const float*)d_in[0];
    const float* rlnw = (const float*)d_in[1];
    const float* rlnb = (const float*)d_in[2];
    const float* rw   = (const float*)d_in[3];
    const float* rb   = (const float*)d_in[4];
    const float* elnw = (const float*)d_in[5];
    const float* elnb = (const float*)d_in[6];
    const float* w1   = (const float*)d_in[7];
    const float* b1   = (const float*)d_in[8];
    const float* w2   = (const float*)d_in[9];
    const float* b2   = (const float*)d_in[10];
    const float* olnw = (const float*)d_in[11];
    const float* olnb = (const float*)d_in[12];
    float* out = (float*)d_out;

    // one-time host-side resource setup (no device memory allocation)
    static cudaStream_t s2 = 0;
    static cudaEvent_t ev0 = 0, evA = 0, evB = 0;
    if (s2 == 0) {
        cudaStreamCreateWithFlags(&s2, cudaStreamNonBlocking);
        cudaEventCreateWithFlags(&ev0, cudaEventDisableTiming);
        cudaEventCreateWithFlags(&evA, cudaEventDisableTiming);
        cudaEventCreateWithFlags(&evB, cudaEventDisableTiming);
        cudaFuncSetAttribute(gemm1_cp_kernel, cudaFuncAttributeMaxDynamicSharedMemorySize, SMEM_DYN);
        cudaFuncSetAttribute(gemm2_cp_kernel, cudaFuncAttributeMaxDynamicSharedMemorySize, SMEM_DYN);
    }

    unsigned short* w1f = 0; cudaGetSymbolAddress((void**)&w1f, g_w1f);
    unsigned short* w2f = 0; cudaGetSymbolAddress((void**)&w2f, g_w2f);

    const int wtotal4 = E_NUM * H_DIM * I_DIM / 4;

    // fork: weight conversions on side stream, router chain on main stream
    cudaEventRecord(ev0, 0);
    cudaStreamWaitEvent(s2, ev0, 0);
    split_w_kernel<<<wtotal4 / 256, 256, 0, s2>>>(w1, w1f, wtotal4);
    cudaEventRecord(evA, s2);
    split_w_kernel<<<wtotal4 / 256, 256, 0, s2>>>(w2, w2f, wtotal4);
    cudaEventRecord(evB, s2);

    init_kernel<<<1, 32>>>();
    router_kernel<<<T_TOK, 256>>>(x, rlnw, rlnb, rw, rb);
    assign_all_kernel<<<1, 1024>>>();
    build_a1_kernel<<<TOTAL_SLOTS, 256>>>(elnw, elnb);

    cudaStreamWaitEvent(0, evA, 0);   // w1f ready
    gemm1_cp_kernel<<<dim3(I_DIM / 128, 32, E_NUM), 256, SMEM_DYN>>>(b1);
    cudaStreamWaitEvent(0, evB, 0);   // w2f ready
    gemm2_cp_kernel<<<dim3(H_DIM / 128, 32, E_NUM), 256, SMEM_DYN>>>(b2);
    combine_ln_kernel<<<T_TOK, 256>>>(olnw, olnb, out);
}